// round 7
// baseline (speedup 1.0000x reference)
#include <cuda_runtime.h>
#include <cuda_bf16.h>
#include <cstdint>
#include <math.h>

#define BB      128
#define DD      (512*512)          // 262144
#define KT      64                 // k elements per stage
#define NTILES  (DD/KT)            // 4096
#define NCTA    148
#define THREADS 512
#define STAGES  3

// ---- scratch (__device__ globals; allocation-free rule) ----
__device__ float g_part[(size_t)NCTA*BB*BB];   // per-CTA partial dots [c][m][n]
__device__ float g_xn2p[NCTA*BB];
__device__ float g_yn2p[NCTA*BB];
__device__ float g_dots[BB*BB];
__device__ float g_xn2[BB];
__device__ float g_yn2[BB];
__device__ int   g_it1, g_it10, g_tick;

__device__ __forceinline__ uint32_t smem_u32(const void* p) {
    uint32_t a;
    asm("{ .reg .u64 t; cvta.to.shared.u64 t, %1; cvt.u32.u64 %0, t; }" : "=r"(a) : "l"(p));
    return a;
}
#define SW128(o) ((uint32_t)(o) ^ ((((uint32_t)(o)) >> 3) & 0x70))

// named barriers: FULL[p] = 1+p, FREE[p] = 1+STAGES+p  (id 0 reserved)
#define BAR_SYNC(id)   asm volatile("bar.sync %0, %1;"   :: "r"(id), "r"(THREADS) : "memory")
#define BAR_ARRIVE(id) asm volatile("bar.arrive %0, %1;" :: "r"(id), "r"(THREADS) : "memory")

// fp32 pair -> packed bf16x2 hi + bf16x2 lo (memory order [a,b], a in low half)
__device__ __forceinline__ void cvt_hilo(float a, float b, uint32_t& h, uint32_t& l) {
    asm("cvt.rn.bf16x2.f32 %0, %1, %2;" : "=r"(h) : "f"(b), "f"(a));
    float fa = __uint_as_float(h << 16);
    float fb = __uint_as_float(h & 0xffff0000u);
    float la = a - fa, lb = b - fb;
    asm("cvt.rn.bf16x2.f32 %0, %1, %2;" : "=r"(l) : "f"(lb), "f"(la));
}

#define LDSM4(r, addr)                                                          \
    asm volatile("ldmatrix.sync.aligned.m8n8.x4.shared.b16 {%0,%1,%2,%3}, [%4];"\
        : "=r"((r)[0]), "=r"((r)[1]), "=r"((r)[2]), "=r"((r)[3]) : "r"(addr))

#define MMA16816(d, a0, a1, a2, a3, b0, b1)                                     \
    asm volatile("mma.sync.aligned.m16n8k16.row.col.f32.bf16.bf16.f32 "         \
        "{%0,%1,%2,%3}, {%4,%5,%6,%7}, {%8,%9}, {%0,%1,%2,%3};"                 \
        : "+f"((d)[0]), "+f"((d)[1]), "+f"((d)[2]), "+f"((d)[3])                \
        : "r"(a0), "r"(a1), "r"(a2), "r"(a3), "r"(b0), "r"(b1))

// SMEM: STAGES x 4 tiles (Xh,Xl,Yh,Yl), each 128 rows x 128B (SW128) = 16KB
#define TILE_OFF(p, w) ((p)*65536 + (w)*16384)
#define SMEM_TOTAL (STAGES*65536)

__global__ void __launch_bounds__(THREADS, 1)
gemm_tc_kernel(const float* __restrict__ X, const float* __restrict__ Y) {
    extern __shared__ char smem[];
    const uint32_t sbase = smem_u32(smem);
    const int t    = threadIdx.x;
    const int lane = t & 31;
    const int w    = t >> 5;          // warps 0-7: consumers (MMA); 8-15: producers
    const int c    = blockIdx.x;

    const int t0 = (int)(((long long)c       * NTILES) / NCTA);
    const int t1 = (int)(((long long)(c + 1) * NTILES) / NCTA);
    const int NT = t1 - t0;

    if (w < 8) {
        // ---------------- CONSUMER: 32x64 output tile per warp ----------------
        const int rb = (w >> 1) * 32;     // row band
        const int cb = (w & 1) * 64;      // col half

        const int a_row = rb + (lane & 7) + ((lane >> 3) & 1) * 8;
        const int a_kb  = ((lane >> 4) & 1) * 16;
        const int b_row = cb + (lane & 7) + ((lane >> 3) & 1) * 8;
        const int b_kb  = ((lane >> 4) & 1) * 16;

        float acc[16][4];
        #pragma unroll
        for (int j = 0; j < 16; j++)
            #pragma unroll
            for (int q = 0; q < 4; q++) acc[j][q] = 0.0f;

        int p = 0;
        for (int s = 0; s < NT; s++) {
            BAR_SYNC(1 + p);                      // wait FULL[p]
            const uint32_t xh = sbase + TILE_OFF(p, 0);
            const uint32_t xl = sbase + TILE_OFF(p, 1);
            const uint32_t yh = sbase + TILE_OFF(p, 2);
            const uint32_t yl = sbase + TILE_OFF(p, 3);
            #pragma unroll
            for (int kk = 0; kk < 4; kk++) {
                uint32_t ah[8], al[8];
                const uint32_t aoff0 = SW128(a_row * 128 + kk * 32 + a_kb);
                const uint32_t aoff1 = SW128((a_row + 16) * 128 + kk * 32 + a_kb);
                LDSM4(ah + 0, xh + aoff0);
                LDSM4(ah + 4, xh + aoff1);
                LDSM4(al + 0, xl + aoff0);
                LDSM4(al + 4, xl + aoff1);
                #pragma unroll
                for (int nh = 0; nh < 2; nh++) {
                    uint32_t bh[8], bl[8];
                    const uint32_t boff0 = SW128((b_row + nh * 32) * 128 + kk * 32 + b_kb);
                    const uint32_t boff1 = SW128((b_row + nh * 32 + 16) * 128 + kk * 32 + b_kb);
                    LDSM4(bh + 0, yh + boff0);
                    LDSM4(bh + 4, yh + boff1);
                    LDSM4(bl + 0, yl + boff0);
                    LDSM4(bl + 4, yl + boff1);
                    // term order: hh, hl, lh (R5 ordering)
                    #pragma unroll
                    for (int m = 0; m < 2; m++) {
                        MMA16816(acc[m*8+nh*4+0], ah[m*4+0],ah[m*4+1],ah[m*4+2],ah[m*4+3], bh[0], bh[2]);
                        MMA16816(acc[m*8+nh*4+1], ah[m*4+0],ah[m*4+1],ah[m*4+2],ah[m*4+3], bh[1], bh[3]);
                        MMA16816(acc[m*8+nh*4+2], ah[m*4+0],ah[m*4+1],ah[m*4+2],ah[m*4+3], bh[4], bh[6]);
                        MMA16816(acc[m*8+nh*4+3], ah[m*4+0],ah[m*4+1],ah[m*4+2],ah[m*4+3], bh[5], bh[7]);
                    }
                    #pragma unroll
                    for (int m = 0; m < 2; m++) {
                        MMA16816(acc[m*8+nh*4+0], ah[m*4+0],ah[m*4+1],ah[m*4+2],ah[m*4+3], bl[0], bl[2]);
                        MMA16816(acc[m*8+nh*4+1], ah[m*4+0],ah[m*4+1],ah[m*4+2],ah[m*4+3], bl[1], bl[3]);
                        MMA16816(acc[m*8+nh*4+2], ah[m*4+0],ah[m*4+1],ah[m*4+2],ah[m*4+3], bl[4], bl[6]);
                        MMA16816(acc[m*8+nh*4+3], ah[m*4+0],ah[m*4+1],ah[m*4+2],ah[m*4+3], bl[5], bl[7]);
                    }
                    #pragma unroll
                    for (int m = 0; m < 2; m++) {
                        MMA16816(acc[m*8+nh*4+0], al[m*4+0],al[m*4+1],al[m*4+2],al[m*4+3], bh[0], bh[2]);
                        MMA16816(acc[m*8+nh*4+1], al[m*4+0],al[m*4+1],al[m*4+2],al[m*4+3], bh[1], bh[3]);
                        MMA16816(acc[m*8+nh*4+2], al[m*4+0],al[m*4+1],al[m*4+2],al[m*4+3], bh[4], bh[6]);
                        MMA16816(acc[m*8+nh*4+3], al[m*4+0],al[m*4+1],al[m*4+2],al[m*4+3], bh[5], bh[7]);
                    }
                }
            }
            BAR_ARRIVE(1 + STAGES + p);           // release FREE[p]
            p = (p + 1 == STAGES) ? 0 : p + 1;
        }

        // epilogue: per-CTA partial dots
        float* base = &g_part[(size_t)c * (BB * BB)];
        const int r0 = rb + (lane >> 2);
        const int c0 = cb + (lane & 3) * 2;
        #pragma unroll
        for (int m = 0; m < 2; m++)
            #pragma unroll
            for (int nh = 0; nh < 2; nh++)
                #pragma unroll
                for (int jj = 0; jj < 4; jj++) {
                    const int j = m * 8 + nh * 4 + jj;
                    const int col = c0 + nh * 32 + jj * 8;
                    *(float2*)(base + (size_t)(r0 + m*16)     * BB + col) = make_float2(acc[j][0], acc[j][1]);
                    *(float2*)(base + (size_t)(r0 + m*16 + 8) * BB + col) = make_float2(acc[j][2], acc[j][3]);
                }
    } else {
        // ---------------- PRODUCER: load fp32, split hi/lo, store swizzled ----------------
        const int tp   = (w - 8) * 32 + lane;   // 0..255
        const int prow = tp >> 4;               // rows prow + 16*i, i<8
        const int pf4  = tp & 15;

        float snx[8], sny[8];
        #pragma unroll
        for (int i = 0; i < 8; i++) { snx[i] = 0.f; sny[i] = 0.f; }

        float4 vx[8], vy[8];

        auto load_regs = [&](int kt) {
            const long long kb = (long long)kt * KT + pf4 * 4;
            #pragma unroll
            for (int i = 0; i < 8; i++) {
                const int row = prow + 16 * i;
                vx[i] = __ldg((const float4*)(X + (long long)row * DD + kb));
                vy[i] = __ldg((const float4*)(Y + (long long)row * DD + kb));
            }
        };
        auto store_stage = [&](int p) {
            char* xh = smem + TILE_OFF(p, 0);
            char* xl = smem + TILE_OFF(p, 1);
            char* yh = smem + TILE_OFF(p, 2);
            char* yl = smem + TILE_OFF(p, 3);
            #pragma unroll
            for (int i = 0; i < 8; i++) {
                const int row = prow + 16 * i;
                const uint32_t off = SW128(row * 128 + pf4 * 8);
                const float4 v = vx[i];
                snx[i] += v.x*v.x + v.y*v.y + v.z*v.z + v.w*v.w;
                uint32_t h0, l0, h1, l1;
                cvt_hilo(v.x, v.y, h0, l0);
                cvt_hilo(v.z, v.w, h1, l1);
                *(uint2*)(xh + off) = make_uint2(h0, h1);
                *(uint2*)(xl + off) = make_uint2(l0, l1);
                const float4 u = vy[i];
                sny[i] += u.x*u.x + u.y*u.y + u.z*u.z + u.w*u.w;
                cvt_hilo(u.x, u.y, h0, l0);
                cvt_hilo(u.z, u.w, h1, l1);
                *(uint2*)(yh + off) = make_uint2(h0, h1);
                *(uint2*)(yl + off) = make_uint2(l0, l1);
            }
        };

        int p = 0;
        for (int sp = 0; sp < NT; sp++) {
            load_regs(t0 + sp);                   // LDGs fly before the wait
            if (sp >= STAGES) BAR_SYNC(1 + STAGES + p);   // wait FREE[p]
            store_stage(p);
            BAR_ARRIVE(1 + p);                    // signal FULL[p]
            p = (p + 1 == STAGES) ? 0 : p + 1;
        }

        // norm partials: 16 consecutive lanes share each row set
        #pragma unroll
        for (int i = 0; i < 8; i++) {
            float a = snx[i], b = sny[i];
            #pragma unroll
            for (int o = 8; o >= 1; o >>= 1) {
                a += __shfl_xor_sync(0xffffffffu, a, o);
                b += __shfl_xor_sync(0xffffffffu, b, o);
            }
            if (pf4 == 0) {
                const int row = prow + 16 * i;
                g_xn2p[c * BB + row] = a;
                g_yn2p[c * BB + row] = b;
            }
        }
    }
}

// deterministic cross-CTA reduction, float4-wide; also zeroes finalize counters
__global__ void reduce_kernel() {
    const int i4 = blockIdx.x * blockDim.x + threadIdx.x;   // 0..4095
    if (i4 == 0) { g_it1 = 0; g_it10 = 0; g_tick = 0; }
    float4 s = make_float4(0.f, 0.f, 0.f, 0.f);
    #pragma unroll 4
    for (int c = 0; c < NCTA; c++) {
        const float4 v = *(const float4*)&g_part[(size_t)c * (BB * BB) + i4 * 4];
        s.x += v.x; s.y += v.y; s.z += v.z; s.w += v.w;
    }
    *(float4*)&g_dots[i4 * 4] = s;
    if (i4 < BB) {
        float s2 = 0.f;
        #pragma unroll 8
        for (int c = 0; c < NCTA; c++) s2 += g_xn2p[c * BB + i4];
        g_xn2[i4] = s2;
    } else if (i4 < 2 * BB) {
        const int r = i4 - BB;
        float s2 = 0.f;
        #pragma unroll 8
        for (int c = 0; c < NCTA; c++) s2 += g_yn2p[c * BB + r];
        g_yn2[r] = s2;
    }
}

// parallel finalize: CTA j handles sim column j (post-transpose row j).
// v_i = dots[i][j] / max(xn_i * yn_j, eps). JAX ties: lower index wins.
__global__ void finalize_kernel(float* __restrict__ out) {
    __shared__ float s_vd;
    __shared__ int s_gt, s_eqb;
    const int j = blockIdx.x;
    const int i = threadIdx.x;

    const float ynj = sqrtf(g_yn2[j]);
    const float xni = sqrtf(g_xn2[i]);
    const float v = g_dots[i * BB + j] / fmaxf(xni * ynj, 1e-8f);

    if (i == 0) { s_gt = 0; s_eqb = 0; }
    if (i == j) s_vd = v;
    __syncthreads();
    const float vd = s_vd;

    const bool gt  = (i != j) && (v > vd);
    const bool eqb = (i != j) && (v == vd) && (i < j);
    const unsigned mgt  = __ballot_sync(0xffffffffu, gt);
    const unsigned meqb = __ballot_sync(0xffffffffu, eqb);
    if ((i & 31) == 0) {
        if (mgt)  atomicAdd(&s_gt,  __popc(mgt));
        if (meqb) atomicAdd(&s_eqb, __popc(meqb));
    }
    __syncthreads();

    if (i == 0) {
        const int rank = s_gt + s_eqb;
        atomicAdd(&g_it1,  (rank == 0) ? 1 : 0);
        atomicAdd(&g_it10, (rank < 10) ? 1 : 0);
        __threadfence();
        const int tick = atomicAdd(&g_tick, 1);
        if (tick == BB - 1) {
            __threadfence();
            out[0] = (float)g_it1  / (float)BB;
            out[1] = (float)g_it10 / (float)BB;
        }
    }
}

extern "C" void kernel_launch(void* const* d_in, const int* in_sizes, int n_in,
                              void* d_out, int out_size) {
    const float* Z = (const float*)d_in[0];
    const float* Y = (const float*)d_in[1];
    float* out = (float*)d_out;

    cudaFuncSetAttribute(gemm_tc_kernel, cudaFuncAttributeMaxDynamicSharedMemorySize, SMEM_TOTAL);
    gemm_tc_kernel<<<NCTA, THREADS, SMEM_TOTAL>>>(Z, Y);
    reduce_kernel<<<32, 128>>>();
    finalize_kernel<<<BB, BB>>>(out);
}

// round 8
// speedup vs baseline: 1.1483x; 1.1483x over previous
#include <cuda_runtime.h>
#include <cuda_bf16.h>
#include <cstdint>
#include <math.h>

#define BB      128
#define DD      (512*512)          // 262144
#define KT      64                 // k elements per stage
#define NTILES  (DD/KT)            // 4096
#define NCTA    148
#define THREADS 512

// ---- scratch (__device__ globals; allocation-free rule) ----
__device__ float g_part[(size_t)NCTA*BB*BB];   // per-CTA partial dots [c][m][n]
__device__ float g_xn2p[NCTA*BB];
__device__ float g_yn2p[NCTA*BB];
__device__ float g_dots[BB*BB];
__device__ float g_xn2[BB];
__device__ float g_yn2[BB];
__device__ int   g_it1, g_it10, g_tick;

__device__ __forceinline__ uint32_t smem_u32(const void* p) {
    uint32_t a;
    asm("{ .reg .u64 t; cvta.to.shared.u64 t, %1; cvt.u32.u64 %0, t; }" : "=r"(a) : "l"(p));
    return a;
}
#define SW128(o) ((uint32_t)(o) ^ ((((uint32_t)(o)) >> 3) & 0x70))

// fp32 pair -> packed bf16x2 hi + bf16x2 lo (memory order [a,b], a in low half)
__device__ __forceinline__ void cvt_hilo(float a, float b, uint32_t& h, uint32_t& l) {
    asm("cvt.rn.bf16x2.f32 %0, %1, %2;" : "=r"(h) : "f"(b), "f"(a));
    float fa = __uint_as_float(h << 16);
    float fb = __uint_as_float(h & 0xffff0000u);
    float la = a - fa, lb = b - fb;
    asm("cvt.rn.bf16x2.f32 %0, %1, %2;" : "=r"(l) : "f"(lb), "f"(la));
}

#define LDSM4(r, addr)                                                          \
    asm volatile("ldmatrix.sync.aligned.m8n8.x4.shared.b16 {%0,%1,%2,%3}, [%4];"\
        : "=r"((r)[0]), "=r"((r)[1]), "=r"((r)[2]), "=r"((r)[3]) : "r"(addr))

#define MMA16816(d, a0, a1, a2, a3, b0, b1)                                     \
    asm volatile("mma.sync.aligned.m16n8k16.row.col.f32.bf16.bf16.f32 "         \
        "{%0,%1,%2,%3}, {%4,%5,%6,%7}, {%8,%9}, {%0,%1,%2,%3};"                 \
        : "+f"((d)[0]), "+f"((d)[1]), "+f"((d)[2]), "+f"((d)[3])                \
        : "r"(a0), "r"(a1), "r"(a2), "r"(a3), "r"(b0), "r"(b1))

// SMEM: 2 stages x 4 tiles (Xh,Xl,Yh,Yl), each 128 rows x 128B (SW128) = 16KB
#define TILE_OFF(p, w) ((p)*65536 + (w)*16384)
#define SMEM_TOTAL (2*65536)

__global__ void __launch_bounds__(THREADS, 1)
gemm_tc_kernel(const float* __restrict__ X, const float* __restrict__ Y) {
    extern __shared__ char smem[];
    const uint32_t sbase = smem_u32(smem);
    const int t    = threadIdx.x;
    const int lane = t & 31;
    const int w    = t >> 5;          // warps 0-7: consumers (MMA); 8-15: producers
    const int c    = blockIdx.x;

    const int t0 = (int)(((long long)c       * NTILES) / NCTA);
    const int t1 = (int)(((long long)(c + 1) * NTILES) / NCTA);
    const int NT = t1 - t0;

    if (w < 8) {
        // ---------------- CONSUMER: 32x64 output tile per warp ----------------
        const int rb = (w >> 1) * 32;     // row band
        const int cb = (w & 1) * 64;      // col half

        const int a_row = rb + (lane & 7) + ((lane >> 3) & 1) * 8;
        const int a_kb  = ((lane >> 4) & 1) * 16;
        const int b_row = cb + (lane & 7) + ((lane >> 3) & 1) * 8;
        const int b_kb  = ((lane >> 4) & 1) * 16;

        float acc[16][4];
        #pragma unroll
        for (int j = 0; j < 16; j++)
            #pragma unroll
            for (int q = 0; q < 4; q++) acc[j][q] = 0.0f;

        __syncthreads();   // stage 0 ready

        for (int s = 0; s < NT; s++) {
            const int p = s & 1;
            const uint32_t xh = sbase + TILE_OFF(p, 0);
            const uint32_t xl = sbase + TILE_OFF(p, 1);
            const uint32_t yh = sbase + TILE_OFF(p, 2);
            const uint32_t yl = sbase + TILE_OFF(p, 3);
            #pragma unroll
            for (int kk = 0; kk < 4; kk++) {
                uint32_t ah[8], al[8];
                const uint32_t aoff0 = SW128(a_row * 128 + kk * 32 + a_kb);
                const uint32_t aoff1 = SW128((a_row + 16) * 128 + kk * 32 + a_kb);
                LDSM4(ah + 0, xh + aoff0);
                LDSM4(ah + 4, xh + aoff1);
                LDSM4(al + 0, xl + aoff0);
                LDSM4(al + 4, xl + aoff1);
                #pragma unroll
                for (int nh = 0; nh < 2; nh++) {
                    uint32_t bh[8], bl[8];
                    const uint32_t boff0 = SW128((b_row + nh * 32) * 128 + kk * 32 + b_kb);
                    const uint32_t boff1 = SW128((b_row + nh * 32 + 16) * 128 + kk * 32 + b_kb);
                    LDSM4(bh + 0, yh + boff0);
                    LDSM4(bh + 4, yh + boff1);
                    LDSM4(bl + 0, yl + boff0);
                    LDSM4(bl + 4, yl + boff1);
                    // term order: hh, hl, lh (R5 champion ordering)
                    #pragma unroll
                    for (int m = 0; m < 2; m++) {
                        MMA16816(acc[m*8+nh*4+0], ah[m*4+0],ah[m*4+1],ah[m*4+2],ah[m*4+3], bh[0], bh[2]);
                        MMA16816(acc[m*8+nh*4+1], ah[m*4+0],ah[m*4+1],ah[m*4+2],ah[m*4+3], bh[1], bh[3]);
                        MMA16816(acc[m*8+nh*4+2], ah[m*4+0],ah[m*4+1],ah[m*4+2],ah[m*4+3], bh[4], bh[6]);
                        MMA16816(acc[m*8+nh*4+3], ah[m*4+0],ah[m*4+1],ah[m*4+2],ah[m*4+3], bh[5], bh[7]);
                    }
                    #pragma unroll
                    for (int m = 0; m < 2; m++) {
                        MMA16816(acc[m*8+nh*4+0], ah[m*4+0],ah[m*4+1],ah[m*4+2],ah[m*4+3], bl[0], bl[2]);
                        MMA16816(acc[m*8+nh*4+1], ah[m*4+0],ah[m*4+1],ah[m*4+2],ah[m*4+3], bl[1], bl[3]);
                        MMA16816(acc[m*8+nh*4+2], ah[m*4+0],ah[m*4+1],ah[m*4+2],ah[m*4+3], bl[4], bl[6]);
                        MMA16816(acc[m*8+nh*4+3], ah[m*4+0],ah[m*4+1],ah[m*4+2],ah[m*4+3], bl[5], bl[7]);
                    }
                    #pragma unroll
                    for (int m = 0; m < 2; m++) {
                        MMA16816(acc[m*8+nh*4+0], al[m*4+0],al[m*4+1],al[m*4+2],al[m*4+3], bh[0], bh[2]);
                        MMA16816(acc[m*8+nh*4+1], al[m*4+0],al[m*4+1],al[m*4+2],al[m*4+3], bh[1], bh[3]);
                        MMA16816(acc[m*8+nh*4+2], al[m*4+0],al[m*4+1],al[m*4+2],al[m*4+3], bh[4], bh[6]);
                        MMA16816(acc[m*8+nh*4+3], al[m*4+0],al[m*4+1],al[m*4+2],al[m*4+3], bh[5], bh[7]);
                    }
                }
            }
            __syncthreads();
        }

        // epilogue: per-CTA partial dots
        float* base = &g_part[(size_t)c * (BB * BB)];
        const int r0 = rb + (lane >> 2);
        const int c0 = cb + (lane & 3) * 2;
        #pragma unroll
        for (int m = 0; m < 2; m++)
            #pragma unroll
            for (int nh = 0; nh < 2; nh++)
                #pragma unroll
                for (int jj = 0; jj < 4; jj++) {
                    const int j = m * 8 + nh * 4 + jj;
                    const int col = c0 + nh * 32 + jj * 8;
                    *(float2*)(base + (size_t)(r0 + m*16)     * BB + col) = make_float2(acc[j][0], acc[j][1]);
                    *(float2*)(base + (size_t)(r0 + m*16 + 8) * BB + col) = make_float2(acc[j][2], acc[j][3]);
                }
    } else {
        // ---------------- PRODUCER: load fp32, split hi/lo, store swizzled ----------------
        const int tp   = (w - 8) * 32 + lane;   // 0..255
        const int prow = tp >> 4;               // rows prow + 16*i, i<8
        const int pf4  = tp & 15;

        float snx[8], sny[8];
        #pragma unroll
        for (int i = 0; i < 8; i++) { snx[i] = 0.f; sny[i] = 0.f; }

        float4 vx[8], vy[8];

        auto load_regs = [&](int kt) {
            const long long kb = (long long)kt * KT + pf4 * 4;
            #pragma unroll
            for (int i = 0; i < 8; i++) {
                const int row = prow + 16 * i;
                vx[i] = __ldg((const float4*)(X + (long long)row * DD + kb));
                vy[i] = __ldg((const float4*)(Y + (long long)row * DD + kb));
            }
        };
        auto store_stage = [&](int p) {
            char* xh = smem + TILE_OFF(p, 0);
            char* xl = smem + TILE_OFF(p, 1);
            char* yh = smem + TILE_OFF(p, 2);
            char* yl = smem + TILE_OFF(p, 3);
            #pragma unroll
            for (int i = 0; i < 8; i++) {
                const int row = prow + 16 * i;
                const uint32_t off = SW128(row * 128 + pf4 * 8);
                const float4 v = vx[i];
                snx[i] += v.x*v.x + v.y*v.y + v.z*v.z + v.w*v.w;
                uint32_t h0, l0, h1, l1;
                cvt_hilo(v.x, v.y, h0, l0);
                cvt_hilo(v.z, v.w, h1, l1);
                *(uint2*)(xh + off) = make_uint2(h0, h1);
                *(uint2*)(xl + off) = make_uint2(l0, l1);
                const float4 u = vy[i];
                sny[i] += u.x*u.x + u.y*u.y + u.z*u.z + u.w*u.w;
                cvt_hilo(u.x, u.y, h0, l0);
                cvt_hilo(u.z, u.w, h1, l1);
                *(uint2*)(yh + off) = make_uint2(h0, h1);
                *(uint2*)(yl + off) = make_uint2(l0, l1);
            }
        };

        load_regs(t0);
        store_stage(0);
        __syncthreads();

        for (int s = 0; s < NT; s++) {
            if (s + 1 < NT) {
                load_regs(t0 + s + 1);
                store_stage((s + 1) & 1);
            }
            __syncthreads();
        }

        // norm partials: 16 consecutive lanes share each row set
        #pragma unroll
        for (int i = 0; i < 8; i++) {
            float a = snx[i], b = sny[i];
            #pragma unroll
            for (int o = 8; o >= 1; o >>= 1) {
                a += __shfl_xor_sync(0xffffffffu, a, o);
                b += __shfl_xor_sync(0xffffffffu, b, o);
            }
            if (pf4 == 0) {
                const int row = prow + 16 * i;
                g_xn2p[c * BB + row] = a;
                g_yn2p[c * BB + row] = b;
            }
        }
    }
}

// deterministic cross-CTA reduction: 16384 threads, coalesced scalar loads, MLP 8
__global__ void reduce_kernel() {
    const int idx = blockIdx.x * blockDim.x + threadIdx.x;   // 0..16383
    if (idx == 0) { g_it1 = 0; g_it10 = 0; g_tick = 0; }
    float s = 0.f;
    #pragma unroll 8
    for (int c = 0; c < NCTA; c++) s += g_part[(size_t)c * (BB * BB) + idx];
    g_dots[idx] = s;
    if (idx < BB) {
        float s2 = 0.f;
        #pragma unroll 8
        for (int c = 0; c < NCTA; c++) s2 += g_xn2p[c * BB + idx];
        g_xn2[idx] = s2;
    } else if (idx < 2 * BB) {
        const int r = idx - BB;
        float s2 = 0.f;
        #pragma unroll 8
        for (int c = 0; c < NCTA; c++) s2 += g_yn2p[c * BB + r];
        g_yn2[r] = s2;
    }
}

// parallel finalize: CTA j handles sim column j (post-transpose row j).
// v_i = dots[i][j] / max(xn_i * yn_j, eps). JAX ties: lower index wins.
__global__ void finalize_kernel(float* __restrict__ out) {
    __shared__ float s_vd;
    __shared__ int s_gt, s_eqb;
    const int j = blockIdx.x;
    const int i = threadIdx.x;

    const float ynj = sqrtf(g_yn2[j]);
    const float xni = sqrtf(g_xn2[i]);
    const float v = g_dots[i * BB + j] / fmaxf(xni * ynj, 1e-8f);

    if (i == 0) { s_gt = 0; s_eqb = 0; }
    if (i == j) s_vd = v;
    __syncthreads();
    const float vd = s_vd;

    const bool gt  = (i != j) && (v > vd);
    const bool eqb = (i != j) && (v == vd) && (i < j);
    const unsigned mgt  = __ballot_sync(0xffffffffu, gt);
    const unsigned meqb = __ballot_sync(0xffffffffu, eqb);
    if ((i & 31) == 0) {
        if (mgt)  atomicAdd(&s_gt,  __popc(mgt));
        if (meqb) atomicAdd(&s_eqb, __popc(meqb));
    }
    __syncthreads();

    if (i == 0) {
        const int rank = s_gt + s_eqb;
        atomicAdd(&g_it1,  (rank == 0) ? 1 : 0);
        atomicAdd(&g_it10, (rank < 10) ? 1 : 0);
        __threadfence();
        const int tick = atomicAdd(&g_tick, 1);
        if (tick == BB - 1) {
            __threadfence();
            out[0] = (float)g_it1  / (float)BB;
            out[1] = (float)g_it10 / (float)BB;
        }
    }
}

extern "C" void kernel_launch(void* const* d_in, const int* in_sizes, int n_in,
                              void* d_out, int out_size) {
    const float* Z = (const float*)d_in[0];
    const float* Y = (const float*)d_in[1];
    float* out = (float*)d_out;

    cudaFuncSetAttribute(gemm_tc_kernel, cudaFuncAttributeMaxDynamicSharedMemorySize, SMEM_TOTAL);
    gemm_tc_kernel<<<NCTA, THREADS, SMEM_TOTAL>>>(Z, Y);
    reduce_kernel<<<128, 128>>>();
    finalize_kernel<<<BB, BB>>>(out);
}

// round 9
// speedup vs baseline: 1.1514x; 1.0027x over previous
#include <cuda_runtime.h>
#include <cuda_bf16.h>
#include <cstdint>
#include <math.h>

#define BB      128
#define DD      (512*512)          // 262144
#define KT      64                 // k elements per stage
#define NTILES  (DD/KT)            // 4096
#define NCTA    148
#define THREADS 512

// ---- scratch (__device__ globals; allocation-free rule) ----
__device__ float g_part[(size_t)NCTA*BB*BB];   // per-CTA partial dots [c][m][n]
__device__ float g_xn2p[NCTA*BB];
__device__ float g_yn2p[NCTA*BB];
__device__ float g_dots[BB*BB];
__device__ float g_xn2[BB];
__device__ float g_yn2[BB];
__device__ int   g_it1, g_it10, g_tick;

__device__ __forceinline__ uint32_t smem_u32(const void* p) {
    uint32_t a;
    asm("{ .reg .u64 t; cvta.to.shared.u64 t, %1; cvt.u32.u64 %0, t; }" : "=r"(a) : "l"(p));
    return a;
}
#define SW128(o) ((uint32_t)(o) ^ ((((uint32_t)(o)) >> 3) & 0x70))

// fp32 pair -> packed bf16x2 hi + bf16x2 lo (memory order [a,b], a in low half)
__device__ __forceinline__ void cvt_hilo(float a, float b, uint32_t& h, uint32_t& l) {
    asm("cvt.rn.bf16x2.f32 %0, %1, %2;" : "=r"(h) : "f"(b), "f"(a));
    float fa = __uint_as_float(h << 16);
    float fb = __uint_as_float(h & 0xffff0000u);
    float la = a - fa, lb = b - fb;
    asm("cvt.rn.bf16x2.f32 %0, %1, %2;" : "=r"(l) : "f"(lb), "f"(la));
}

#define LDSM4(r, addr)                                                          \
    asm volatile("ldmatrix.sync.aligned.m8n8.x4.shared.b16 {%0,%1,%2,%3}, [%4];"\
        : "=r"((r)[0]), "=r"((r)[1]), "=r"((r)[2]), "=r"((r)[3]) : "r"(addr))

#define MMA16816(d, a0, a1, a2, a3, b0, b1)                                     \
    asm volatile("mma.sync.aligned.m16n8k16.row.col.f32.bf16.bf16.f32 "         \
        "{%0,%1,%2,%3}, {%4,%5,%6,%7}, {%8,%9}, {%0,%1,%2,%3};"                 \
        : "+f"((d)[0]), "+f"((d)[1]), "+f"((d)[2]), "+f"((d)[3])                \
        : "r"(a0), "r"(a1), "r"(a2), "r"(a3), "r"(b0), "r"(b1))

// SMEM: 2 stages x 4 tiles (Xh,Xl,Yh,Yl), each 128 rows x 128B (SW128) = 16KB
#define TILE_OFF(p, w) ((p)*65536 + (w)*16384)
#define SMEM_TOTAL (2*65536)

__global__ void __launch_bounds__(THREADS, 1)
gemm_tc_kernel(const float* __restrict__ X, const float* __restrict__ Y) {
    extern __shared__ char smem[];
    const uint32_t sbase = smem_u32(smem);
    const int t    = threadIdx.x;
    const int lane = t & 31;
    const int w    = t >> 5;          // warps 0-7: producers; 8-15: consumers (hi-wid priority)
    const int c    = blockIdx.x;

    const int t0 = (int)(((long long)c       * NTILES) / NCTA);
    const int t1 = (int)(((long long)(c + 1) * NTILES) / NCTA);
    const int NT = t1 - t0;

    if (w >= 8) {
        // ---------------- CONSUMER: 32x64 output tile per warp (R8 champion loop) ----------------
        const int cw = w - 8;
        const int rb = (cw >> 1) * 32;     // row band
        const int cb = (cw & 1) * 64;      // col half

        const int a_row = rb + (lane & 7) + ((lane >> 3) & 1) * 8;
        const int a_kb  = ((lane >> 4) & 1) * 16;
        const int b_row = cb + (lane & 7) + ((lane >> 3) & 1) * 8;
        const int b_kb  = ((lane >> 4) & 1) * 16;

        float acc[16][4];
        #pragma unroll
        for (int j = 0; j < 16; j++)
            #pragma unroll
            for (int q = 0; q < 4; q++) acc[j][q] = 0.0f;

        __syncthreads();   // stage 0 ready

        for (int s = 0; s < NT; s++) {
            const int p = s & 1;
            const uint32_t xh = sbase + TILE_OFF(p, 0);
            const uint32_t xl = sbase + TILE_OFF(p, 1);
            const uint32_t yh = sbase + TILE_OFF(p, 2);
            const uint32_t yl = sbase + TILE_OFF(p, 3);
            #pragma unroll
            for (int kk = 0; kk < 4; kk++) {
                uint32_t ah[8], al[8];
                const uint32_t aoff0 = SW128(a_row * 128 + kk * 32 + a_kb);
                const uint32_t aoff1 = SW128((a_row + 16) * 128 + kk * 32 + a_kb);
                LDSM4(ah + 0, xh + aoff0);
                LDSM4(ah + 4, xh + aoff1);
                LDSM4(al + 0, xl + aoff0);
                LDSM4(al + 4, xl + aoff1);
                #pragma unroll
                for (int nh = 0; nh < 2; nh++) {
                    uint32_t bh[8], bl[8];
                    const uint32_t boff0 = SW128((b_row + nh * 32) * 128 + kk * 32 + b_kb);
                    const uint32_t boff1 = SW128((b_row + nh * 32 + 16) * 128 + kk * 32 + b_kb);
                    LDSM4(bh + 0, yh + boff0);
                    LDSM4(bh + 4, yh + boff1);
                    LDSM4(bl + 0, yl + boff0);
                    LDSM4(bl + 4, yl + boff1);
                    // term order: hh, hl, lh (champion ordering)
                    #pragma unroll
                    for (int m = 0; m < 2; m++) {
                        MMA16816(acc[m*8+nh*4+0], ah[m*4+0],ah[m*4+1],ah[m*4+2],ah[m*4+3], bh[0], bh[2]);
                        MMA16816(acc[m*8+nh*4+1], ah[m*4+0],ah[m*4+1],ah[m*4+2],ah[m*4+3], bh[1], bh[3]);
                        MMA16816(acc[m*8+nh*4+2], ah[m*4+0],ah[m*4+1],ah[m*4+2],ah[m*4+3], bh[4], bh[6]);
                        MMA16816(acc[m*8+nh*4+3], ah[m*4+0],ah[m*4+1],ah[m*4+2],ah[m*4+3], bh[5], bh[7]);
                    }
                    #pragma unroll
                    for (int m = 0; m < 2; m++) {
                        MMA16816(acc[m*8+nh*4+0], ah[m*4+0],ah[m*4+1],ah[m*4+2],ah[m*4+3], bl[0], bl[2]);
                        MMA16816(acc[m*8+nh*4+1], ah[m*4+0],ah[m*4+1],ah[m*4+2],ah[m*4+3], bl[1], bl[3]);
                        MMA16816(acc[m*8+nh*4+2], ah[m*4+0],ah[m*4+1],ah[m*4+2],ah[m*4+3], bl[4], bl[6]);
                        MMA16816(acc[m*8+nh*4+3], ah[m*4+0],ah[m*4+1],ah[m*4+2],ah[m*4+3], bl[5], bl[7]);
                    }
                    #pragma unroll
                    for (int m = 0; m < 2; m++) {
                        MMA16816(acc[m*8+nh*4+0], al[m*4+0],al[m*4+1],al[m*4+2],al[m*4+3], bh[0], bh[2]);
                        MMA16816(acc[m*8+nh*4+1], al[m*4+0],al[m*4+1],al[m*4+2],al[m*4+3], bh[1], bh[3]);
                        MMA16816(acc[m*8+nh*4+2], al[m*4+0],al[m*4+1],al[m*4+2],al[m*4+3], bh[4], bh[6]);
                        MMA16816(acc[m*8+nh*4+3], al[m*4+0],al[m*4+1],al[m*4+2],al[m*4+3], bh[5], bh[7]);
                    }
                }
            }
            __syncthreads();
        }

        // epilogue: per-CTA partial dots
        float* base = &g_part[(size_t)c * (BB * BB)];
        const int r0 = rb + (lane >> 2);
        const int c0 = cb + (lane & 3) * 2;
        #pragma unroll
        for (int m = 0; m < 2; m++)
            #pragma unroll
            for (int nh = 0; nh < 2; nh++)
                #pragma unroll
                for (int jj = 0; jj < 4; jj++) {
                    const int j = m * 8 + nh * 4 + jj;
                    const int col = c0 + nh * 32 + jj * 8;
                    *(float2*)(base + (size_t)(r0 + m*16)     * BB + col) = make_float2(acc[j][0], acc[j][1]);
                    *(float2*)(base + (size_t)(r0 + m*16 + 8) * BB + col) = make_float2(acc[j][2], acc[j][3]);
                }
    } else {
        // ---------------- PRODUCER: LDG two stages ahead, store one ahead ----------------
        const int tp   = w * 32 + lane;         // 0..255
        const int prow = tp >> 4;               // rows prow + 16*i, i<8
        const int pf4  = tp & 15;

        float snx[8], sny[8];
        #pragma unroll
        for (int i = 0; i < 8; i++) { snx[i] = 0.f; sny[i] = 0.f; }

        // two half-batches: half h covers i = 4h .. 4h+3
        float4 vx[2][4], vy[2][4];

        auto load_half = [&](int kt, int h) {
            const long long kb = (long long)kt * KT + pf4 * 4;
            #pragma unroll
            for (int i = 0; i < 4; i++) {
                const int row = prow + 16 * (4 * h + i);
                vx[h][i] = __ldg((const float4*)(X + (long long)row * DD + kb));
                vy[h][i] = __ldg((const float4*)(Y + (long long)row * DD + kb));
            }
        };
        auto store_half = [&](int p, int h) {
            char* xh = smem + TILE_OFF(p, 0);
            char* xl = smem + TILE_OFF(p, 1);
            char* yh = smem + TILE_OFF(p, 2);
            char* yl = smem + TILE_OFF(p, 3);
            #pragma unroll
            for (int i = 0; i < 4; i++) {
                const int ii = 4 * h + i;
                const int row = prow + 16 * ii;
                const uint32_t off = SW128(row * 128 + pf4 * 8);
                const float4 v = vx[h][i];
                snx[ii] += v.x*v.x + v.y*v.y + v.z*v.z + v.w*v.w;
                uint32_t h0, l0, h1, l1;
                cvt_hilo(v.x, v.y, h0, l0);
                cvt_hilo(v.z, v.w, h1, l1);
                *(uint2*)(xh + off) = make_uint2(h0, h1);
                *(uint2*)(xl + off) = make_uint2(l0, l1);
                const float4 u = vy[h][i];
                sny[ii] += u.x*u.x + u.y*u.y + u.z*u.z + u.w*u.w;
                cvt_hilo(u.x, u.y, h0, l0);
                cvt_hilo(u.z, u.w, h1, l1);
                *(uint2*)(yh + off) = make_uint2(h0, h1);
                *(uint2*)(yl + off) = make_uint2(l0, l1);
            }
        };

        // prologue: stage 0 into buf0 (cold stall acceptable once), stage 1 LDGs in flight
        load_half(t0, 0); load_half(t0, 1);
        store_half(0, 0); store_half(0, 1);
        if (NT > 1) { load_half(t0 + 1, 0); load_half(t0 + 1, 1); }
        __syncthreads();   // stage 0 ready

        for (int s = 0; s < NT; s++) {
            if (s + 1 < NT) {
                const int p = (s + 1) & 1;
                store_half(p, 0);                      // data loaded during stage s-1: ready
                if (s + 2 < NT) load_half(t0 + s + 2, 0);
                store_half(p, 1);
                if (s + 2 < NT) load_half(t0 + s + 2, 1);
            }
            __syncthreads();
        }

        // norm partials: 16 consecutive lanes share each row set
        #pragma unroll
        for (int i = 0; i < 8; i++) {
            float a = snx[i], b = sny[i];
            #pragma unroll
            for (int o = 8; o >= 1; o >>= 1) {
                a += __shfl_xor_sync(0xffffffffu, a, o);
                b += __shfl_xor_sync(0xffffffffu, b, o);
            }
            if (pf4 == 0) {
                const int row = prow + 16 * i;
                g_xn2p[c * BB + row] = a;
                g_yn2p[c * BB + row] = b;
            }
        }
    }
}

// deterministic cross-CTA reduction: 16384 threads, coalesced scalar loads, MLP 8
__global__ void reduce_kernel() {
    const int idx = blockIdx.x * blockDim.x + threadIdx.x;   // 0..16383
    if (idx == 0) { g_it1 = 0; g_it10 = 0; g_tick = 0; }
    float s = 0.f;
    #pragma unroll 8
    for (int c = 0; c < NCTA; c++) s += g_part[(size_t)c * (BB * BB) + idx];
    g_dots[idx] = s;
    if (idx < BB) {
        float s2 = 0.f;
        #pragma unroll 8
        for (int c = 0; c < NCTA; c++) s2 += g_xn2p[c * BB + idx];
        g_xn2[idx] = s2;
    } else if (idx < 2 * BB) {
        const int r = idx - BB;
        float s2 = 0.f;
        #pragma unroll 8
        for (int c = 0; c < NCTA; c++) s2 += g_yn2p[c * BB + r];
        g_yn2[r] = s2;
    }
}

// parallel finalize: CTA j handles sim column j (post-transpose row j).
// v_i = dots[i][j] / max(xn_i * yn_j, eps). JAX ties: lower index wins.
__global__ void finalize_kernel(float* __restrict__ out) {
    __shared__ float s_vd;
    __shared__ int s_gt, s_eqb;
    const int j = blockIdx.x;
    const int i = threadIdx.x;

    const float ynj = sqrtf(g_yn2[j]);
    const float xni = sqrtf(g_xn2[i]);
    const float v = g_dots[i * BB + j] / fmaxf(xni * ynj, 1e-8f);

    if (i == 0) { s_gt = 0; s_eqb = 0; }
    if (i == j) s_vd = v;
    __syncthreads();
    const float vd = s_vd;

    const bool gt  = (i != j) && (v > vd);
    const bool eqb = (i != j) && (v == vd) && (i < j);
    const unsigned mgt  = __ballot_sync(0xffffffffu, gt);
    const unsigned meqb = __ballot_sync(0xffffffffu, eqb);
    if ((i & 31) == 0) {
        if (mgt)  atomicAdd(&s_gt,  __popc(mgt));
        if (meqb) atomicAdd(&s_eqb, __popc(meqb));
    }
    __syncthreads();

    if (i == 0) {
        const int rank = s_gt + s_eqb;
        atomicAdd(&g_it1,  (rank == 0) ? 1 : 0);
        atomicAdd(&g_it10, (rank < 10) ? 1 : 0);
        __threadfence();
        const int tick = atomicAdd(&g_tick, 1);
        if (tick == BB - 1) {
            __threadfence();
            out[0] = (float)g_it1  / (float)BB;
            out[1] = (float)g_it10 / (float)BB;
        }
    }
}

extern "C" void kernel_launch(void* const* d_in, const int* in_sizes, int n_in,
                              void* d_out, int out_size) {
    const float* Z = (const float*)d_in[0];
    const float* Y = (const float*)d_in[1];
    float* out = (float*)d_out;

    cudaFuncSetAttribute(gemm_tc_kernel, cudaFuncAttributeMaxDynamicSharedMemorySize, SMEM_TOTAL);
    gemm_tc_kernel<<<NCTA, THREADS, SMEM_TOTAL>>>(Z, Y);
    reduce_kernel<<<128, 128>>>();
    finalize_kernel<<<BB, BB>>>(out);
}

// round 10
// speedup vs baseline: 1.2905x; 1.1208x over previous
#include <cuda_runtime.h>
#include <cuda_bf16.h>
#include <cstdint>
#include <math.h>

#define BB      128
#define DD      (512*512)          // 262144
#define KT      64                 // k elements per stage
#define NTILES  (DD/KT)            // 4096
#define NCTA    148
#define THREADS 512
#define NCH     4                  // reduction chunks (148 = 4*37)
#define CPC     37                 // CTAs per chunk

// ---- scratch (__device__ globals; allocation-free rule) ----
__device__ float g_part[(size_t)NCTA*BB*BB];   // per-CTA partial dots [c][m][n]
__device__ float g_xn2p[NCTA*BB];
__device__ float g_yn2p[NCTA*BB];
__device__ float g_p2[BB*BB*NCH];              // chunked dots [idx][ch]
__device__ float g_xc[BB*NCH];                 // chunked xn2  [i][ch]
__device__ float g_yc[BB*NCH];                 // chunked yn2  [j][ch]
__device__ int   g_it1, g_it10, g_tick;

__device__ __forceinline__ uint32_t smem_u32(const void* p) {
    uint32_t a;
    asm("{ .reg .u64 t; cvta.to.shared.u64 t, %1; cvt.u32.u64 %0, t; }" : "=r"(a) : "l"(p));
    return a;
}
#define SW128(o) ((uint32_t)(o) ^ ((((uint32_t)(o)) >> 3) & 0x70))

// fp32 pair -> packed bf16x2 hi + bf16x2 lo (memory order [a,b], a in low half)
__device__ __forceinline__ void cvt_hilo(float a, float b, uint32_t& h, uint32_t& l) {
    asm("cvt.rn.bf16x2.f32 %0, %1, %2;" : "=r"(h) : "f"(b), "f"(a));
    float fa = __uint_as_float(h << 16);
    float fb = __uint_as_float(h & 0xffff0000u);
    float la = a - fa, lb = b - fb;
    asm("cvt.rn.bf16x2.f32 %0, %1, %2;" : "=r"(l) : "f"(lb), "f"(la));
}

#define LDSM4(r, addr)                                                          \
    asm volatile("ldmatrix.sync.aligned.m8n8.x4.shared.b16 {%0,%1,%2,%3}, [%4];"\
        : "=r"((r)[0]), "=r"((r)[1]), "=r"((r)[2]), "=r"((r)[3]) : "r"(addr))

#define MMA16816(d, a0, a1, a2, a3, b0, b1)                                     \
    asm volatile("mma.sync.aligned.m16n8k16.row.col.f32.bf16.bf16.f32 "         \
        "{%0,%1,%2,%3}, {%4,%5,%6,%7}, {%8,%9}, {%0,%1,%2,%3};"                 \
        : "+f"((d)[0]), "+f"((d)[1]), "+f"((d)[2]), "+f"((d)[3])                \
        : "r"(a0), "r"(a1), "r"(a2), "r"(a3), "r"(b0), "r"(b1))

// SMEM: 2 stages x 4 tiles (Xh,Xl,Yh,Yl), each 128 rows x 128B (SW128) = 16KB
#define TILE_OFF(p, w) ((p)*65536 + (w)*16384)
#define SMEM_TOTAL (2*65536)

__global__ void __launch_bounds__(THREADS, 1)
gemm_tc_kernel(const float* __restrict__ X, const float* __restrict__ Y) {
    extern __shared__ char smem[];
    const uint32_t sbase = smem_u32(smem);
    const int t    = threadIdx.x;
    const int lane = t & 31;
    const int w    = t >> 5;          // warps 0-7: producers; 8-15: consumers (hi-wid priority)
    const int c    = blockIdx.x;

    const int t0 = (int)(((long long)c       * NTILES) / NCTA);
    const int t1 = (int)(((long long)(c + 1) * NTILES) / NCTA);
    const int NT = t1 - t0;

    if (w >= 8) {
        // ---------------- CONSUMER: 32x64 output tile per warp (champion loop) ----------------
        const int cw = w - 8;
        const int rb = (cw >> 1) * 32;     // row band
        const int cb = (cw & 1) * 64;      // col half

        const int a_row = rb + (lane & 7) + ((lane >> 3) & 1) * 8;
        const int a_kb  = ((lane >> 4) & 1) * 16;
        const int b_row = cb + (lane & 7) + ((lane >> 3) & 1) * 8;
        const int b_kb  = ((lane >> 4) & 1) * 16;

        float acc[16][4];
        #pragma unroll
        for (int j = 0; j < 16; j++)
            #pragma unroll
            for (int q = 0; q < 4; q++) acc[j][q] = 0.0f;

        __syncthreads();   // stage 0 ready

        for (int s = 0; s < NT; s++) {
            const int p = s & 1;
            const uint32_t xh = sbase + TILE_OFF(p, 0);
            const uint32_t xl = sbase + TILE_OFF(p, 1);
            const uint32_t yh = sbase + TILE_OFF(p, 2);
            const uint32_t yl = sbase + TILE_OFF(p, 3);
            #pragma unroll
            for (int kk = 0; kk < 4; kk++) {
                uint32_t ah[8], al[8];
                const uint32_t aoff0 = SW128(a_row * 128 + kk * 32 + a_kb);
                const uint32_t aoff1 = SW128((a_row + 16) * 128 + kk * 32 + a_kb);
                LDSM4(ah + 0, xh + aoff0);
                LDSM4(ah + 4, xh + aoff1);
                LDSM4(al + 0, xl + aoff0);
                LDSM4(al + 4, xl + aoff1);
                #pragma unroll
                for (int nh = 0; nh < 2; nh++) {
                    uint32_t bh[8], bl[8];
                    const uint32_t boff0 = SW128((b_row + nh * 32) * 128 + kk * 32 + b_kb);
                    const uint32_t boff1 = SW128((b_row + nh * 32 + 16) * 128 + kk * 32 + b_kb);
                    LDSM4(bh + 0, yh + boff0);
                    LDSM4(bh + 4, yh + boff1);
                    LDSM4(bl + 0, yl + boff0);
                    LDSM4(bl + 4, yl + boff1);
                    // term order: hh, hl, lh (champion ordering)
                    #pragma unroll
                    for (int m = 0; m < 2; m++) {
                        MMA16816(acc[m*8+nh*4+0], ah[m*4+0],ah[m*4+1],ah[m*4+2],ah[m*4+3], bh[0], bh[2]);
                        MMA16816(acc[m*8+nh*4+1], ah[m*4+0],ah[m*4+1],ah[m*4+2],ah[m*4+3], bh[1], bh[3]);
                        MMA16816(acc[m*8+nh*4+2], ah[m*4+0],ah[m*4+1],ah[m*4+2],ah[m*4+3], bh[4], bh[6]);
                        MMA16816(acc[m*8+nh*4+3], ah[m*4+0],ah[m*4+1],ah[m*4+2],ah[m*4+3], bh[5], bh[7]);
                    }
                    #pragma unroll
                    for (int m = 0; m < 2; m++) {
                        MMA16816(acc[m*8+nh*4+0], ah[m*4+0],ah[m*4+1],ah[m*4+2],ah[m*4+3], bl[0], bl[2]);
                        MMA16816(acc[m*8+nh*4+1], ah[m*4+0],ah[m*4+1],ah[m*4+2],ah[m*4+3], bl[1], bl[3]);
                        MMA16816(acc[m*8+nh*4+2], ah[m*4+0],ah[m*4+1],ah[m*4+2],ah[m*4+3], bl[4], bl[6]);
                        MMA16816(acc[m*8+nh*4+3], ah[m*4+0],ah[m*4+1],ah[m*4+2],ah[m*4+3], bl[5], bl[7]);
                    }
                    #pragma unroll
                    for (int m = 0; m < 2; m++) {
                        MMA16816(acc[m*8+nh*4+0], al[m*4+0],al[m*4+1],al[m*4+2],al[m*4+3], bh[0], bh[2]);
                        MMA16816(acc[m*8+nh*4+1], al[m*4+0],al[m*4+1],al[m*4+2],al[m*4+3], bh[1], bh[3]);
                        MMA16816(acc[m*8+nh*4+2], al[m*4+0],al[m*4+1],al[m*4+2],al[m*4+3], bh[4], bh[6]);
                        MMA16816(acc[m*8+nh*4+3], al[m*4+0],al[m*4+1],al[m*4+2],al[m*4+3], bh[5], bh[7]);
                    }
                }
            }
            __syncthreads();
        }

        // epilogue: per-CTA partial dots
        float* base = &g_part[(size_t)c * (BB * BB)];
        const int r0 = rb + (lane >> 2);
        const int c0 = cb + (lane & 3) * 2;
        #pragma unroll
        for (int m = 0; m < 2; m++)
            #pragma unroll
            for (int nh = 0; nh < 2; nh++)
                #pragma unroll
                for (int jj = 0; jj < 4; jj++) {
                    const int j = m * 8 + nh * 4 + jj;
                    const int col = c0 + nh * 32 + jj * 8;
                    *(float2*)(base + (size_t)(r0 + m*16)     * BB + col) = make_float2(acc[j][0], acc[j][1]);
                    *(float2*)(base + (size_t)(r0 + m*16 + 8) * BB + col) = make_float2(acc[j][2], acc[j][3]);
                }
    } else {
        // ---------------- PRODUCER: LDG two stages ahead, store one ahead ----------------
        const int tp   = w * 32 + lane;         // 0..255
        const int prow = tp >> 4;               // rows prow + 16*i, i<8
        const int pf4  = tp & 15;

        float snx[8], sny[8];
        #pragma unroll
        for (int i = 0; i < 8; i++) { snx[i] = 0.f; sny[i] = 0.f; }

        float4 vx[2][4], vy[2][4];

        auto load_half = [&](int kt, int h) {
            const long long kb = (long long)kt * KT + pf4 * 4;
            #pragma unroll
            for (int i = 0; i < 4; i++) {
                const int row = prow + 16 * (4 * h + i);
                vx[h][i] = __ldg((const float4*)(X + (long long)row * DD + kb));
                vy[h][i] = __ldg((const float4*)(Y + (long long)row * DD + kb));
            }
        };
        auto store_half = [&](int p, int h) {
            char* xh = smem + TILE_OFF(p, 0);
            char* xl = smem + TILE_OFF(p, 1);
            char* yh = smem + TILE_OFF(p, 2);
            char* yl = smem + TILE_OFF(p, 3);
            #pragma unroll
            for (int i = 0; i < 4; i++) {
                const int ii = 4 * h + i;
                const int row = prow + 16 * ii;
                const uint32_t off = SW128(row * 128 + pf4 * 8);
                const float4 v = vx[h][i];
                snx[ii] += v.x*v.x + v.y*v.y + v.z*v.z + v.w*v.w;
                uint32_t h0, l0, h1, l1;
                cvt_hilo(v.x, v.y, h0, l0);
                cvt_hilo(v.z, v.w, h1, l1);
                *(uint2*)(xh + off) = make_uint2(h0, h1);
                *(uint2*)(xl + off) = make_uint2(l0, l1);
                const float4 u = vy[h][i];
                sny[ii] += u.x*u.x + u.y*u.y + u.z*u.z + u.w*u.w;
                cvt_hilo(u.x, u.y, h0, l0);
                cvt_hilo(u.z, u.w, h1, l1);
                *(uint2*)(yh + off) = make_uint2(h0, h1);
                *(uint2*)(yl + off) = make_uint2(l0, l1);
            }
        };

        load_half(t0, 0); load_half(t0, 1);
        store_half(0, 0); store_half(0, 1);
        if (NT > 1) { load_half(t0 + 1, 0); load_half(t0 + 1, 1); }
        __syncthreads();   // stage 0 ready

        for (int s = 0; s < NT; s++) {
            if (s + 1 < NT) {
                const int p = (s + 1) & 1;
                store_half(p, 0);
                if (s + 2 < NT) load_half(t0 + s + 2, 0);
                store_half(p, 1);
                if (s + 2 < NT) load_half(t0 + s + 2, 1);
            }
            __syncthreads();
        }

        // norm partials: 16 consecutive lanes share each row set
        #pragma unroll
        for (int i = 0; i < 8; i++) {
            float a = snx[i], b = sny[i];
            #pragma unroll
            for (int o = 8; o >= 1; o >>= 1) {
                a += __shfl_xor_sync(0xffffffffu, a, o);
                b += __shfl_xor_sync(0xffffffffu, b, o);
            }
            if (pf4 == 0) {
                const int row = prow + 16 * i;
                g_xn2p[c * BB + row] = a;
                g_yn2p[c * BB + row] = b;
            }
        }
    }
}

// Phase A: chunked reduction. 65536 threads: chunk ch sums CTAs [ch*37, ch*37+37).
// Coalesced loads (idx contiguous within a chunk). Deterministic fixed order.
__global__ void reduce_kernel() {
    const int gid = blockIdx.x * blockDim.x + threadIdx.x;   // 0..65535
    const int ch  = gid >> 14;          // 0..3
    const int idx = gid & 16383;        // 0..16383
    if (gid == 0) { g_it1 = 0; g_it10 = 0; g_tick = 0; }
    const int c0 = ch * CPC;
    float s = 0.f;
    #pragma unroll
    for (int k = 0; k < CPC; k++) s += g_part[(size_t)(c0 + k) * (BB * BB) + idx];
    g_p2[idx * NCH + ch] = s;
    if (idx < BB) {
        float s2 = 0.f;
        #pragma unroll
        for (int k = 0; k < CPC; k++) s2 += g_xn2p[(c0 + k) * BB + idx];
        g_xc[idx * NCH + ch] = s2;
    } else if (idx < 2 * BB) {
        const int r = idx - BB;
        float s2 = 0.f;
        #pragma unroll
        for (int k = 0; k < CPC; k++) s2 += g_yn2p[(c0 + k) * BB + r];
        g_yc[r * NCH + ch] = s2;
    }
}

// parallel finalize: CTA j handles sim column j (post-transpose row j).
// v_i = dots[i][j] / max(xn_i * yn_j, eps). JAX ties: lower index wins.
__global__ void finalize_kernel(float* __restrict__ out) {
    __shared__ float s_vd;
    __shared__ int s_gt, s_eqb;
    const int j = blockIdx.x;
    const int i = threadIdx.x;

    const float4 dv = *(const float4*)&g_p2[(i * BB + j) * NCH];
    const float dots = (dv.x + dv.y) + (dv.z + dv.w);
    const float4 xv = *(const float4*)&g_xc[i * NCH];
    const float xni = sqrtf((xv.x + xv.y) + (xv.z + xv.w));
    const float4 yv = *(const float4*)&g_yc[j * NCH];
    const float ynj = sqrtf((yv.x + yv.y) + (yv.z + yv.w));
    const float v = dots / fmaxf(xni * ynj, 1e-8f);

    if (i == 0) { s_gt = 0; s_eqb = 0; }
    if (i == j) s_vd = v;
    __syncthreads();
    const float vd = s_vd;

    const bool gt  = (i != j) && (v > vd);
    const bool eqb = (i != j) && (v == vd) && (i < j);
    const unsigned mgt  = __ballot_sync(0xffffffffu, gt);
    const unsigned meqb = __ballot_sync(0xffffffffu, eqb);
    if ((i & 31) == 0) {
        if (mgt)  atomicAdd(&s_gt,  __popc(mgt));
        if (meqb) atomicAdd(&s_eqb, __popc(meqb));
    }
    __syncthreads();

    if (i == 0) {
        const int rank = s_gt + s_eqb;
        atomicAdd(&g_it1,  (rank == 0) ? 1 : 0);
        atomicAdd(&g_it10, (rank < 10) ? 1 : 0);
        __threadfence();
        const int tick = atomicAdd(&g_tick, 1);
        if (tick == BB - 1) {
            __threadfence();
            out[0] = (float)g_it1  / (float)BB;
            out[1] = (float)g_it10 / (float)BB;
        }
    }
}

extern "C" void kernel_launch(void* const* d_in, const int* in_sizes, int n_in,
                              void* d_out, int out_size) {
    const float* Z = (const float*)d_in[0];
    const float* Y = (const float*)d_in[1];
    float* out = (float*)d_out;

    cudaFuncSetAttribute(gemm_tc_kernel, cudaFuncAttributeMaxDynamicSharedMemorySize, SMEM_TOTAL);
    gemm_tc_kernel<<<NCTA, THREADS, SMEM_TOTAL>>>(Z, Y);
    reduce_kernel<<<256, 256>>>();
    finalize_kernel<<<BB, BB>>>(out);
}